// round 5
// baseline (speedup 1.0000x reference)
#include <cuda_runtime.h>

// Scratch buffers.
__device__ float g_part[64 * 9216];    // stage1: [z=64][i*1152+c]  (2.36 MB)
__device__ float g_part2[8 * 9216];    // stage2: [g=8][i*1152+c]   (295 KB)
__device__ float g_us[1152 * 160];     // batch-summed u_hat        (737 KB)

// Stage 1: g_part[z][e] = sum of 4 batches (z*4 .. z*4+3) of x[b][e].
// x: [256, 9216] f32 = [256, 2304] float4. Four loads into DISTINCT float4
// registers so they issue back-to-back (true MLP=4 per thread).
__global__ void __launch_bounds__(256) reduce_x1_kernel(const float* __restrict__ x) {
    const int col = blockIdx.x * 256 + threadIdx.x;   // 0..2303 float4 cols
    const int z = blockIdx.y;                         // 0..63
    const float4* p = reinterpret_cast<const float4*>(x) + (size_t)(z * 4) * 2304 + col;
    const float4 v0 = __ldg(p);
    const float4 v1 = __ldg(p + 2304);
    const float4 v2 = __ldg(p + 2 * 2304);
    const float4 v3 = __ldg(p + 3 * 2304);
    float4 a;
    a.x = (v0.x + v1.x) + (v2.x + v3.x);
    a.y = (v0.y + v1.y) + (v2.y + v3.y);
    a.z = (v0.z + v1.z) + (v2.z + v3.z);
    a.w = (v0.w + v1.w) + (v2.w + v3.w);
    reinterpret_cast<float4*>(g_part)[(size_t)z * 2304 + col] = a;
}

// Stage 2: g_part2[g][e] = sum_{j<8} g_part[g*8+j][e].  All L2-resident.
__global__ void __launch_bounds__(256) reduce_x2_kernel() {
    const int e = blockIdx.x * 256 + threadIdx.x;     // 0..9215
    const int g = blockIdx.y;                         // 0..7
    const float* p = g_part + (size_t)(g * 8) * 9216 + e;
    float a0 = p[0],        a1 = p[9216],     a2 = p[2 * 9216], a3 = p[3 * 9216];
    float a4 = p[4 * 9216], a5 = p[5 * 9216], a6 = p[6 * 9216], a7 = p[7 * 9216];
    g_part2[(size_t)g * 9216 + e] = ((a0 + a1) + (a2 + a3)) + ((a4 + a5) + (a6 + a7));
}

// Stage 3: pure streaming GEMV. us[c,u,s] = sum_i W[c,u,s,i] * xs[i][c].
__global__ void __launch_bounds__(160) us_kernel(const float* __restrict__ W) {
    const int c = blockIdx.x;
    const int t = threadIdx.x;

    __shared__ float xs[8];

    const float4* wp = reinterpret_cast<const float4*>(W + (size_t)c * 1280) + 2 * t;
    const float4 w0 = __ldg(wp);
    const float4 w1 = __ldg(wp + 1);

    if (t < 8) {
        const float* p = g_part2 + t * 1152 + c;
        float a0 = p[0],        a1 = p[9216],     a2 = p[2 * 9216], a3 = p[3 * 9216];
        float a4 = p[4 * 9216], a5 = p[5 * 9216], a6 = p[6 * 9216], a7 = p[7 * 9216];
        xs[t] = ((a0 + a1) + (a2 + a3)) + ((a4 + a5) + (a6 + a7));
    }
    __syncthreads();

    g_us[(size_t)c * 160 + t] =
          w0.x * xs[0] + w0.y * xs[1] + w0.z * xs[2] + w0.w * xs[3]
        + w1.x * xs[4] + w1.y * xs[5] + w1.z * xs[6] + w1.w * xs[7];
}

// Stage 4: routing — one WARP per capsule, zero barriers / zero smem.
// Lane owns 5 (u,s): t = k*32+lane, u = 2k + (lane>>4), s = lane&15.
__global__ void __launch_bounds__(256) routing_kernel(float* __restrict__ out) {
    const int warp = threadIdx.x >> 5;
    const int lane = threadIdx.x & 31;
    const int c = blockIdx.x * 8 + warp;     // 144 * 8 = 1152
    const int h = lane >> 4;                 // u parity

    float us[5];
    #pragma unroll
    for (int k = 0; k < 5; ++k)
        us[k] = g_us[(size_t)c * 160 + k * 32 + lane];  // coalesced L2 hits

    float be[5] = {0.f, 0.f, 0.f, 0.f, 0.f};
    float bo[5] = {0.f, 0.f, 0.f, 0.f, 0.f};
    float cij[5] = {0.1f, 0.1f, 0.1f, 0.1f, 0.1f};  // softmax(0) = 1/10 exactly
    float v[5];

    #pragma unroll
    for (int it = 0; it < 3; ++it) {
        #pragma unroll
        for (int k = 0; k < 5; ++k) {
            const float sj = cij[k] * us[k];

            float msq = sj * sj;                 // ||s_j||^2 over 16 s-lanes
            #pragma unroll
            for (int off = 8; off; off >>= 1)
                msq += __shfl_xor_sync(0xffffffffu, msq, off);

            v[k] = msq / (1.0f + msq) * sj * rsqrtf(msq);

            if (it < 2) {
                float a = us[k] * v[k];          // agreement over s
                #pragma unroll
                for (int off = 8; off; off >>= 1)
                    a += __shfl_xor_sync(0xffffffffu, a, off);
                a *= (1.0f / 256.0f);
                const float ap = __shfl_xor_sync(0xffffffffu, a, 16);
                be[k] += h ? ap : a;
                bo[k] += h ? a : ap;
            }
        }

        if (it < 2) {
            float m = be[0];
            #pragma unroll
            for (int k = 0; k < 5; ++k) { m = fmaxf(m, be[k]); m = fmaxf(m, bo[k]); }
            float ee[5], eo[5], denom = 0.f;
            #pragma unroll
            for (int k = 0; k < 5; ++k) {
                ee[k] = __expf(be[k] - m);
                eo[k] = __expf(bo[k] - m);
                denom += ee[k] + eo[k];
            }
            const float inv = 1.0f / denom;
            #pragma unroll
            for (int k = 0; k < 5; ++k)
                cij[k] = (h ? eo[k] : ee[k]) * inv;
        }
    }

    #pragma unroll
    for (int k = 0; k < 5; ++k)
        out[(size_t)c * 160 + k * 32 + lane] = v[k];
}

extern "C" void kernel_launch(void* const* d_in, const int* in_sizes, int n_in,
                              void* d_out, int out_size) {
    const float* x = (const float*)d_in[0];   // [256, 8, 1152]
    const float* W = (const float*)d_in[1];   // [1, 1152, 10, 16, 8]
    float* out = (float*)d_out;               // [1152, 10, 16]

    reduce_x1_kernel<<<dim3(9, 64), 256>>>(x);
    reduce_x2_kernel<<<dim3(36, 8), 256>>>();
    us_kernel<<<1152, 160>>>(W);
    routing_kernel<<<144, 256>>>(out);
}

// round 6
// speedup vs baseline: 1.1905x; 1.1905x over previous
#include <cuda_runtime.h>

// Stage-1 partial batch sums of x: [z=64][i*1152+c]  (2.36 MB)
__device__ float g_part[64 * 9216];

// Stage 1: g_part[z][e] = sum of batches z*4..z*4+3 of x[b][e].
// x: [256, 9216] f32 = [256, 2304] float4; 4 loads into distinct regs (MLP=4).
__global__ void __launch_bounds__(256) reduce_x1_kernel(const float* __restrict__ x) {
    const int col = blockIdx.x * 256 + threadIdx.x;   // 0..2303 float4 cols
    const int z = blockIdx.y;                         // 0..63
    const float4* p = reinterpret_cast<const float4*>(x) + (size_t)(z * 4) * 2304 + col;
    const float4 v0 = __ldg(p);
    const float4 v1 = __ldg(p + 2304);
    const float4 v2 = __ldg(p + 2 * 2304);
    const float4 v3 = __ldg(p + 3 * 2304);
    float4 a;
    a.x = (v0.x + v1.x) + (v2.x + v3.x);
    a.y = (v0.y + v1.y) + (v2.y + v3.y);
    a.z = (v0.z + v1.z) + (v2.z + v3.z);
    a.w = (v0.w + v1.w) + (v2.w + v3.w);
    reinterpret_cast<float4*>(g_part)[(size_t)z * 2304 + col] = a;
}

// Stage 2 (fused): per capsule c — finish xs, compute us = W·xs, run routing.
// Block = 160 threads. Routing runs on warp 0 only: lane -> u, all 16 s-values
// in registers, so the only cross-lane traffic is the 8-shuffle softmax.
__global__ void __launch_bounds__(160, 8) fused_kernel(const float* __restrict__ W,
                                                       float* __restrict__ out) {
    const int c = blockIdx.x;       // 1152
    const int t = threadIdx.x;      // 0..159

    __shared__ float xs_p[64];
    __shared__ float xs[8];
    __shared__ __align__(16) float us_sm[160];

    // Kick off the big W stream immediately (2 coalesced LDG.128 / thread).
    const float4* wp = reinterpret_cast<const float4*>(W + (size_t)c * 1280) + 2 * t;
    const float4 w0 = __ldg(wp);
    const float4 w1 = __ldg(wp + 1);

    // xs[i][c]: 64 threads each sum 8 of the 64 z-partials (MLP=8, L2 hits).
    if (t < 64) {
        const int i = t & 7;
        const int zg = t >> 3;
        const float* p = g_part + (size_t)(zg * 8) * 9216 + i * 1152 + c;
        const float b0 = p[0],        b1 = p[9216],     b2 = p[2 * 9216], b3 = p[3 * 9216];
        const float b4 = p[4 * 9216], b5 = p[5 * 9216], b6 = p[6 * 9216], b7 = p[7 * 9216];
        xs_p[t] = ((b0 + b1) + (b2 + b3)) + ((b4 + b5) + (b6 + b7));
    }
    __syncthreads();
    if (t < 8) {
        float a = 0.f;
        #pragma unroll
        for (int zg = 0; zg < 8; ++zg) a += xs_p[zg * 8 + t];
        xs[t] = a;
    }
    __syncthreads();

    // us[c,u,s] into smem (t = u*16 + s)
    us_sm[t] = w0.x * xs[0] + w0.y * xs[1] + w0.z * xs[2] + w0.w * xs[3]
             + w1.x * xs[4] + w1.y * xs[5] + w1.z * xs[6] + w1.w * xs[7];
    __syncthreads();

    // ── Routing on warp 0: lane -> u (16-lane groups; lanes 16-31 mirror) ──
    if (t < 32) {
        const int u = t & 15;
        const bool act = (t < 16) && (u < 10);

        // All 16 s-values of u_sum for this u, in registers.
        const float4* up = reinterpret_cast<const float4*>(us_sm + (u < 10 ? u : 0) * 16);
        const float4 q0 = up[0], q1 = up[1], q2 = up[2], q3 = up[3];
        float us[16] = {q0.x, q0.y, q0.z, q0.w, q1.x, q1.y, q1.z, q1.w,
                        q2.x, q2.y, q2.z, q2.w, q3.x, q3.y, q3.z, q3.w};

        float b = (u < 10) ? 0.f : -1e30f;   // invalid lanes never win the max
        float cij = 0.1f;                    // softmax of zero logits, exact
        float v[16];

        #pragma unroll
        for (int it = 0; it < 3; ++it) {
            // s_j and ||s_j||^2 — pure register math
            float sj[16], msq = 0.f;
            #pragma unroll
            for (int s = 0; s < 16; ++s) { sj[s] = cij * us[s]; msq += sj[s] * sj[s]; }

            const float coef = msq / (1.0f + msq) * rsqrtf(msq);
            #pragma unroll
            for (int s = 0; s < 16; ++s) v[s] = coef * sj[s];

            if (it < 2) {
                // agreement <u_sum, v> — register tree; guarded for pad lanes
                float a = 0.f;
                #pragma unroll
                for (int s = 0; s < 16; ++s) a += us[s] * v[s];
                if (u < 10) b += a * (1.0f / 256.0f);

                // softmax over u: 4-shfl max + 4-shfl sum inside the 16-lane group
                float m = b;
                #pragma unroll
                for (int off = 8; off; off >>= 1)
                    m = fmaxf(m, __shfl_xor_sync(0xffffffffu, m, off));
                float e = (u < 10) ? __expf(b - m) : 0.f;
                float d = e;
                #pragma unroll
                for (int off = 8; off; off >>= 1)
                    d += __shfl_xor_sync(0xffffffffu, d, off);
                cij = e / d;
            }
        }

        if (act) {
            float4* op = reinterpret_cast<float4*>(out + (size_t)c * 160 + u * 16);
            op[0] = make_float4(v[0],  v[1],  v[2],  v[3]);
            op[1] = make_float4(v[4],  v[5],  v[6],  v[7]);
            op[2] = make_float4(v[8],  v[9],  v[10], v[11]);
            op[3] = make_float4(v[12], v[13], v[14], v[15]);
        }
    }
}

extern "C" void kernel_launch(void* const* d_in, const int* in_sizes, int n_in,
                              void* d_out, int out_size) {
    const float* x = (const float*)d_in[0];   // [256, 8, 1152]
    const float* W = (const float*)d_in[1];   // [1, 1152, 10, 16, 8]
    float* out = (float*)d_out;               // [1152, 10, 16]

    reduce_x1_kernel<<<dim3(9, 64), 256>>>(x);
    fused_kernel<<<1152, 160>>>(W, out);
}

// round 7
// speedup vs baseline: 1.1976x; 1.0060x over previous
#include <cuda_runtime.h>

// Stage-1 partial batch sums of x: [z=64][i*1152+c]  (2.36 MB)
__device__ float g_part[64 * 9216];

// Stage 1: g_part[z][e] = sum of batches z*4..z*4+3 of x[b][e].
// x: [256, 9216] f32 = [256, 2304] float4; 4 loads into distinct regs (MLP=4).
__global__ void __launch_bounds__(256) reduce_x1_kernel(const float* __restrict__ x) {
    const int col = blockIdx.x * 256 + threadIdx.x;   // 0..2303 float4 cols
    const int z = blockIdx.y;                         // 0..63
    const float4* p = reinterpret_cast<const float4*>(x) + (size_t)(z * 4) * 2304 + col;
    const float4 v0 = __ldg(p);
    const float4 v1 = __ldg(p + 2304);
    const float4 v2 = __ldg(p + 2 * 2304);
    const float4 v3 = __ldg(p + 3 * 2304);
    float4 a;
    a.x = (v0.x + v1.x) + (v2.x + v3.x);
    a.y = (v0.y + v1.y) + (v2.y + v3.y);
    a.z = (v0.z + v1.z) + (v2.z + v3.z);
    a.w = (v0.w + v1.w) + (v2.w + v3.w);
    reinterpret_cast<float4*>(g_part)[(size_t)z * 2304 + col] = a;
}

// Stage 2 (fused): per capsule c — xs finish, us = W·xs, scalar-collapsed
// routing on warp 0. NO min-blocks in launch_bounds: registers must not spill.
__global__ void __launch_bounds__(160) fused_kernel(const float* __restrict__ W,
                                                    float* __restrict__ out) {
    const int c = blockIdx.x;       // 1152
    const int t = threadIdx.x;      // 0..159

    __shared__ float xs_p[64];
    __shared__ float xs[8];
    __shared__ __align__(16) float us_sm[160];

    // Kick off the big W stream immediately (2 coalesced LDG.128 / thread).
    const float4* wp = reinterpret_cast<const float4*>(W + (size_t)c * 1280) + 2 * t;
    const float4 w0 = __ldg(wp);
    const float4 w1 = __ldg(wp + 1);

    // xs[i][c]: 64 threads each sum 8 of the 64 z-partials (independent loads).
    if (t < 64) {
        const int i = t & 7;
        const int zg = t >> 3;
        const float* p = g_part + (size_t)(zg * 8) * 9216 + i * 1152 + c;
        const float b0 = p[0],        b1 = p[9216],     b2 = p[2 * 9216], b3 = p[3 * 9216];
        const float b4 = p[4 * 9216], b5 = p[5 * 9216], b6 = p[6 * 9216], b7 = p[7 * 9216];
        xs_p[t] = ((b0 + b1) + (b2 + b3)) + ((b4 + b5) + (b6 + b7));
    }
    __syncthreads();
    if (t < 8) {
        float a = 0.f;
        #pragma unroll
        for (int zg = 0; zg < 8; ++zg) a += xs_p[zg * 8 + t];
        xs[t] = a;
    }
    __syncthreads();

    // us[c,u,s] into smem (t = u*16 + s)
    us_sm[t] = w0.x * xs[0] + w0.y * xs[1] + w0.z * xs[2] + w0.w * xs[3]
             + w1.x * xs[4] + w1.y * xs[5] + w1.z * xs[6] + w1.w * xs[7];
    __syncthreads();

    // ── Routing on warp 0: lane -> u. Scalar recurrence on c_ij:
    //    s_j = c_ij * u_sum  =>  ||s_j||^2 = c_ij^2 * usq  (usq fixed),
    //    agreement = coef * c_ij * usq / B,  v = (coef*c_ij) * u_sum.
    if (t < 32) {
        const int u = t & 15;
        const bool valid = (u < 10);

        const float4* up = reinterpret_cast<const float4*>(us_sm + (valid ? u : 0) * 16);
        const float4 q0 = up[0], q1 = up[1], q2 = up[2], q3 = up[3];
        const float usq =
              (q0.x * q0.x + q0.y * q0.y + q0.z * q0.z + q0.w * q0.w)
            + (q1.x * q1.x + q1.y * q1.y + q1.z * q1.z + q1.w * q1.w)
            + (q2.x * q2.x + q2.y * q2.y + q2.z * q2.z + q2.w * q2.w)
            + (q3.x * q3.x + q3.y * q3.y + q3.z * q3.z + q3.w * q3.w);

        float b = valid ? 0.f : -1e30f;
        float cij = 0.1f;                 // softmax of zero logits, exact
        float k = 0.f;                    // final scale coef*cij

        #pragma unroll
        for (int it = 0; it < 3; ++it) {
            const float msq = cij * cij * usq;
            const float coef = msq / (1.0f + msq) * rsqrtf(msq);
            k = coef * cij;

            if (it < 2) {
                if (valid) b += k * usq * (1.0f / 256.0f);
                // softmax over u inside the 16-lane group (xor offsets < 16)
                float m = b;
                #pragma unroll
                for (int off = 8; off; off >>= 1)
                    m = fmaxf(m, __shfl_xor_sync(0xffffffffu, m, off));
                const float e = valid ? __expf(b - m) : 0.f;
                float d = e;
                #pragma unroll
                for (int off = 8; off; off >>= 1)
                    d += __shfl_xor_sync(0xffffffffu, d, off);
                cij = e / d;
            }
        }

        if (t < 16 && valid) {
            float4* op = reinterpret_cast<float4*>(out + (size_t)c * 160 + u * 16);
            op[0] = make_float4(k * q0.x, k * q0.y, k * q0.z, k * q0.w);
            op[1] = make_float4(k * q1.x, k * q1.y, k * q1.z, k * q1.w);
            op[2] = make_float4(k * q2.x, k * q2.y, k * q2.z, k * q2.w);
            op[3] = make_float4(k * q3.x, k * q3.y, k * q3.z, k * q3.w);
        }
    }
}

extern "C" void kernel_launch(void* const* d_in, const int* in_sizes, int n_in,
                              void* d_out, int out_size) {
    const float* x = (const float*)d_in[0];   // [256, 8, 1152]
    const float* W = (const float*)d_in[1];   // [1, 1152, 10, 16, 8]
    float* out = (float*)d_out;               // [1152, 10, 16]

    reduce_x1_kernel<<<dim3(9, 64), 256>>>(x);
    fused_kernel<<<1152, 160>>>(W, out);
}